// round 1
// baseline (speedup 1.0000x reference)
#include <cuda_runtime.h>
#include <cstdint>
#include <cstddef>

#define WIDTH  2048
#define DEPTH  8
#define DP1    9
#define TMOD   242          // 30*DEPTH + 2
#define WD     16384        // WIDTH*DEPTH
#define NSPLIT 16
#define CHUNK  128          // WIDTH / NSPLIT

// d_out layout (float32, concatenated in reference return order)
#define OFF_OUT   0ULL
#define OFF_STATE 1ULL
#define OFF_SA    18433ULL
#define OFF_SG    4478977ULL
#define OFF_OG    4495361ULL
#define OFF_GRAD  8955905ULL
#define OFF_OWG   42510337ULL

// scratch (allocation-free: __device__ globals)
__device__ float g_hpart[NSPLIT][WD];
__device__ float g_contrib[WIDTH * 8];
__device__ float g_m[WIDTH * 8];
__device__ float g_aprev[WIDTH * 8];

__device__ __forceinline__ int posmod(int v, int m) {
    int r = v % m;
    return r < 0 ? r + m : r;
}

// sa after .at[:,:,time].set(state): read-through with aliasing to new state
__device__ __forceinline__ float sa_eff(const float* __restrict__ sa_in,
                                        const float* __restrict__ out,
                                        int w, int c, int t, int time) {
    if (t == time) return out[OFF_STATE + (size_t)w * DP1 + c];
    return sa_in[((size_t)w * DP1 + c) * TMOD + t];
}

// og after .at[:,:,time].set(output_weights)
__device__ __forceinline__ float og_eff(const float* __restrict__ og_in,
                                        const float* __restrict__ ow,
                                        int w, int c, int t, int time) {
    if (t == time) return ow[(size_t)w * DP1 + c];
    return og_in[((size_t)w * DP1 + c) * TMOD + t];
}

// ---------------------------------------------------------------------------
// K1: hidden partial sums.  hidden_flat[k] = sum_i W[i*WD + k] * state[i, k&7]
// Split the i-reduction NSPLIT ways; partials into g_hpart.
// ---------------------------------------------------------------------------
__global__ void k_hidden_partial(const float* __restrict__ W,
                                 const float* __restrict__ state_in) {
    __shared__ float ss[CHUNK * 8];
    int k = blockIdx.x * blockDim.x + threadIdx.x;   // 0..WD-1
    int i0 = blockIdx.y * CHUNK;

    // stage state[i0:i0+CHUNK, 0:8] into smem
    for (int idx = threadIdx.x; idx < CHUNK * 8; idx += blockDim.x) {
        int i = idx >> 3, d = idx & 7;
        ss[idx] = state_in[(size_t)(i0 + i) * DP1 + d];
    }
    __syncthreads();

    int d = k & 7;
    float acc = 0.f;
    const float* Wp = W + (size_t)i0 * WD + k;
#pragma unroll 8
    for (int i = 0; i < CHUNK; ++i)
        acc = fmaf(Wp[(size_t)i * WD], ss[i * 8 + d], acc);

    g_hpart[blockIdx.y][k] = acc;
}

// ---------------------------------------------------------------------------
// K2: combine partials -> relu -> state (and output_weights_gradient copy)
// ---------------------------------------------------------------------------
__global__ void k_state(float* __restrict__ out, const float* __restrict__ x) {
    int k = blockIdx.x * blockDim.x + threadIdx.x;   // 0..WD-1
    float s = 0.f;
#pragma unroll
    for (int c = 0; c < NSPLIT; ++c) s += g_hpart[c][k];
    s = fmaxf(s, 0.f);
    int w = k >> 3, d = k & 7;
    size_t o = (size_t)w * DP1 + d + 1;
    out[OFF_STATE + o] = s;
    out[OFF_OWG + o]   = s;
    if (d == 0) {
        float xv = x[w];
        out[OFF_STATE + (size_t)w * DP1] = xv;
        out[OFF_OWG   + (size_t)w * DP1] = xv;
    }
}

// ---------------------------------------------------------------------------
// K3: output scalar = sum(output_weights * state_new)
// ---------------------------------------------------------------------------
__global__ void k_output(float* __restrict__ out, const float* __restrict__ ow) {
    const float* st = out + OFF_STATE;
    float acc = 0.f;
    for (int idx = threadIdx.x; idx < WIDTH * DP1; idx += blockDim.x)
        acc += ow[idx] * st[idx];
    __shared__ float red[32];
#pragma unroll
    for (int off = 16; off; off >>= 1)
        acc += __shfl_down_sync(0xffffffffu, acc, off);
    if ((threadIdx.x & 31) == 0) red[threadIdx.x >> 5] = acc;
    __syncthreads();
    if (threadIdx.x < 32) {
        float v = red[threadIdx.x];
#pragma unroll
        for (int off = 16; off; off >>= 1)
            v += __shfl_down_sync(0xffffffffu, v, off);
        if (threadIdx.x == 0) out[OFF_OUT] = v;
    }
}

// ---------------------------------------------------------------------------
// K4: contrib[i,a] = sum_j W[i,j,a+1] * sgrad[j,a+1],  a = 0..6
// One block per i. Row of W is 64KB contiguous; float4 loads.
// ---------------------------------------------------------------------------
__global__ void k_contrib(const float* __restrict__ W,
                          const float* __restrict__ g) {
    int i = blockIdx.x;
    const float4* Wr = reinterpret_cast<const float4*>(W + (size_t)i * WD);
    const float4* gg = reinterpret_cast<const float4*>(g);

    float acc[7] = {0, 0, 0, 0, 0, 0, 0};
    for (int j = threadIdx.x; j < WIDTH; j += blockDim.x) {
        float4 w0 = Wr[j * 2];      // d = 0..3
        float4 w1 = Wr[j * 2 + 1];  // d = 4..7
        float4 g0 = gg[j * 2];
        float4 g1 = gg[j * 2 + 1];
        acc[0] = fmaf(w0.y, g0.y, acc[0]);
        acc[1] = fmaf(w0.z, g0.z, acc[1]);
        acc[2] = fmaf(w0.w, g0.w, acc[2]);
        acc[3] = fmaf(w1.x, g1.x, acc[3]);
        acc[4] = fmaf(w1.y, g1.y, acc[4]);
        acc[5] = fmaf(w1.z, g1.z, acc[5]);
        acc[6] = fmaf(w1.w, g1.w, acc[6]);
    }
    // warp reduce then cross-warp
    __shared__ float red[8][7];
#pragma unroll
    for (int a = 0; a < 7; ++a)
#pragma unroll
        for (int off = 16; off; off >>= 1)
            acc[a] += __shfl_down_sync(0xffffffffu, acc[a], off);
    if ((threadIdx.x & 31) == 0) {
        int w = threadIdx.x >> 5;
#pragma unroll
        for (int a = 0; a < 7; ++a) red[w][a] = acc[a];
    }
    __syncthreads();
    if (threadIdx.x < 7) {
        float s = 0.f;
#pragma unroll
        for (int w = 0; w < 8; ++w) s += red[w][threadIdx.x];
        g_contrib[(size_t)i * 8 + threadIdx.x] = s;
    }
}

// ---------------------------------------------------------------------------
// K5: sa / og full copies with the time-slice replaced (fused, one pass)
// ---------------------------------------------------------------------------
__global__ void k_saog(float* __restrict__ out,
                       const float* __restrict__ sa_in,
                       const float* __restrict__ og_in,
                       const float* __restrict__ ow,
                       const int* __restrict__ time_p) {
    const int time = *time_p;
    const int n = WIDTH * DP1 * TMOD;
    int idx = blockIdx.x * blockDim.x + threadIdx.x;
    if (idx >= n) return;
    int t  = idx % TMOD;
    int wc = idx / TMOD;
    float sav, ogv;
    if (t == time) {
        sav = out[OFF_STATE + wc];   // state already written by k_state
        ogv = ow[wc];
    } else {
        sav = sa_in[idx];
        ogv = og_in[idx];
    }
    out[OFF_SA + idx] = sav;
    out[OFF_OG + idx] = ogv;
}

// ---------------------------------------------------------------------------
// K6: stored-gradients update sg, plus m = sg*relu_g and act_prev for K7
// ---------------------------------------------------------------------------
__global__ void k_sg(float* __restrict__ out,
                     const float* __restrict__ sa_in,
                     const float* __restrict__ og_in,
                     const float* __restrict__ ow,
                     const int* __restrict__ time_p) {
    int idx = blockIdx.x * blockDim.x + threadIdx.x;   // 0..WD-1
    if (idx >= WIDTH * DEPTH) return;
    int i = idx >> 3, a = idx & 7;
    const int time = *time_p;

    int tia = posmod(time - 2 * DEPTH + 2 * (a + 1), TMOD);

    float sgv;
    if (a < DEPTH - 1) {
        int t1 = (tia + 1) % TMOD;
        float rm = (sa_eff(sa_in, out, i, a + 2, t1, time) > 0.f) ? 1.f : 0.f;
        sgv = fmaf(rm, g_contrib[idx], og_eff(og_in, ow, i, a + 1, tia, time));
    } else {
        sgv = og_eff(og_in, ow, i, DEPTH, time, time);  // = ow[i, DEPTH]
    }
    out[OFF_SG + idx] = sgv;

    float rg = (sa_eff(sa_in, out, i, a + 1, tia, time) > 0.f) ? 1.f : 0.f;
    g_m[idx] = sgv * rg;
    g_aprev[idx] = sa_eff(sa_in, out, i, a, posmod(tia - 1, TMOD), time);
}

// ---------------------------------------------------------------------------
// K7: gradients[i,j,a] = act_prev[i,a] * m[j,a]
// Row i flat = ap[k&7] * m_flat[k]  (m layout (j,a) matches gradient inner dims)
// ---------------------------------------------------------------------------
__global__ void k_grad(float* __restrict__ out) {
    int i = blockIdx.x;
    __shared__ float ap[8];
    if (threadIdx.x < 8) ap[threadIdx.x] = g_aprev[(size_t)i * 8 + threadIdx.x];
    __syncthreads();
    float* dst = out + OFF_GRAD + (size_t)i * WD;
#pragma unroll 4
    for (int k = threadIdx.x; k < WD; k += blockDim.x)
        dst[k] = ap[k & 7] * g_m[k];
}

// ---------------------------------------------------------------------------
extern "C" void kernel_launch(void* const* d_in, const int* in_sizes, int n_in,
                              void* d_out, int out_size) {
    const float* x    = (const float*)d_in[0];
    const float* W    = (const float*)d_in[1];
    const float* ow   = (const float*)d_in[2];
    const float* st   = (const float*)d_in[3];
    const float* sa   = (const float*)d_in[4];
    const float* sgr  = (const float*)d_in[5];
    const float* og   = (const float*)d_in[6];
    const int*   tim  = (const int*)d_in[7];
    float* out = (float*)d_out;

    k_hidden_partial<<<dim3(WD / 256, NSPLIT), 256>>>(W, st);
    k_contrib<<<WIDTH, 256>>>(W, sgr);
    k_state<<<WD / 256, 256>>>(out, x);
    k_output<<<1, 1024>>>(out, ow);
    k_saog<<<(WIDTH * DP1 * TMOD + 255) / 256, 256>>>(out, sa, og, ow, tim);
    k_sg<<<WD / 256, 256>>>(out, sa, og, ow, tim);
    k_grad<<<WIDTH, 256>>>(out);
}

// round 2
// speedup vs baseline: 1.0737x; 1.0737x over previous
#include <cuda_runtime.h>
#include <cstdint>
#include <cstddef>

#define WIDTH  2048
#define DEPTH  8
#define DP1    9
#define TMOD   242          // 30*DEPTH + 2
#define WD     16384        // WIDTH*DEPTH
#define NSPLIT 16           // i-splits (blockIdx.y)
#define KBLK   64           // k-blocks  (blockIdx.x)
#define CHUNK  128          // WIDTH / NSPLIT

// d_out layout (float32, concatenated in reference return order)
#define OFF_OUT   0ULL
#define OFF_STATE 1ULL
#define OFF_SA    18433ULL
#define OFF_SG    4478977ULL
#define OFF_OG    4495361ULL
#define OFF_GRAD  8955905ULL
#define OFF_OWG   42510337ULL

// scratch (allocation-free: __device__ globals)
__device__ float g_hpart[NSPLIT][WD];     // hidden partials (1 MB)
__device__ float g_cpart[KBLK][WD];       // contrib partials (4 MB)
__device__ float g_contrib[WD];
__device__ float g_m[WD];
__device__ float g_aprev[WD];
__device__ float g_out_acc;

__device__ __forceinline__ int posmod(int v, int m) {
    int r = v % m;
    return r < 0 ? r + m : r;
}

__device__ __forceinline__ float sa_eff(const float* __restrict__ sa_in,
                                        const float* __restrict__ out,
                                        int w, int c, int t, int time) {
    if (t == time) return out[OFF_STATE + (size_t)w * DP1 + c];
    return sa_in[((size_t)w * DP1 + c) * TMOD + t];
}

__device__ __forceinline__ float og_eff(const float* __restrict__ og_in,
                                        const float* __restrict__ ow,
                                        int w, int c, int t, int time) {
    if (t == time) return ow[(size_t)w * DP1 + c];
    return og_in[((size_t)w * DP1 + c) * TMOD + t];
}

// ---------------------------------------------------------------------------
// K1: SINGLE pass over W computing BOTH reductions.
//   hidden[k]   = sum_i W[i*WD + k] * state[i, k&7]     (column reduce)
//   contrib[i,d]= sum_j W[i*WD + j*8+d] * sg[j*8+d]     (row reduce, d>=1)
// Block (bx, by): k in [bx*256, bx*256+256), i in [by*128, by*128+128)
// ---------------------------------------------------------------------------
__global__ void k_fusedW(const float* __restrict__ W,
                         const float* __restrict__ state_in,
                         const float* __restrict__ sgrad) {
    __shared__ float ss[CHUNK * 8];          // state chunk (4 KB)
    __shared__ float csm[8 * CHUNK * 8];     // per-warp contrib partials (32 KB)

    const int tid = threadIdx.x;
    const int k   = blockIdx.x * 256 + tid;
    const int i0  = blockIdx.y * CHUNK;
    const int wid = tid >> 5, lane = tid & 31;
    const int d   = k & 7;                   // == lane & 7

    if (blockIdx.x == 0 && blockIdx.y == 0 && tid == 0) g_out_acc = 0.f;

    for (int idx = tid; idx < CHUNK * 8; idx += 256) {
        int i = idx >> 3, dd = idx & 7;
        ss[idx] = state_in[(size_t)(i0 + i) * DP1 + dd];
    }
    __syncthreads();

    const float sgf = (d == 0) ? 0.f : sgrad[k];
    const float* Wp = W + (size_t)i0 * WD + k;

    float acc = 0.f;
#pragma unroll 8
    for (int i = 0; i < CHUNK; ++i) {
        float w = Wp[(size_t)i * WD];
        acc = fmaf(w, ss[i * 8 + d], acc);
        float p = w * sgf;
        p += __shfl_xor_sync(0xffffffffu, p, 8);
        p += __shfl_xor_sync(0xffffffffu, p, 16);
        // all lanes now hold the warp's 4-j sum for their d; lanes 0..7 store
        if (lane < 8) csm[(wid * CHUNK + i) * 8 + lane] = p;
    }
    g_hpart[blockIdx.y][k] = acc;

    __syncthreads();
    // reduce 8 warps -> per-block contrib partial for these 128 i's
    for (int idx = tid; idx < CHUNK * 8; idx += 256) {
        float s = 0.f;
#pragma unroll
        for (int w = 0; w < 8; ++w) s += csm[w * CHUNK * 8 + idx];
        g_cpart[blockIdx.x][(size_t)i0 * 8 + idx] = s;
    }
}

// ---------------------------------------------------------------------------
// K2: finalize — state/owg, contrib sum, output dot (atomic partial)
// ---------------------------------------------------------------------------
__global__ void k_finalize(float* __restrict__ out, const float* __restrict__ x,
                           const float* __restrict__ ow) {
    int k = blockIdx.x * blockDim.x + threadIdx.x;   // 0..WD-1
    float s = 0.f;
#pragma unroll
    for (int c = 0; c < NSPLIT; ++c) s += g_hpart[c][k];
    s = fmaxf(s, 0.f);

    float cb = 0.f;
#pragma unroll 8
    for (int b = 0; b < KBLK; ++b) cb += g_cpart[b][k];
    g_contrib[k] = cb;

    int w = k >> 3, dd = k & 7;
    size_t o = (size_t)w * DP1 + dd + 1;
    out[OFF_STATE + o] = s;
    out[OFF_OWG + o]   = s;

    float v = ow[o] * s;
    if (dd == 0) {
        float xv = x[w];
        out[OFF_STATE + (size_t)w * DP1] = xv;
        out[OFF_OWG   + (size_t)w * DP1] = xv;
        v = fmaf(ow[(size_t)w * DP1], xv, v);
    }

    // block reduce v, single atomic per block
    __shared__ float red[8];
#pragma unroll
    for (int off = 16; off; off >>= 1)
        v += __shfl_down_sync(0xffffffffu, v, off);
    if ((threadIdx.x & 31) == 0) red[threadIdx.x >> 5] = v;
    __syncthreads();
    if (threadIdx.x == 0) {
        float t = 0.f;
#pragma unroll
        for (int i = 0; i < 8; ++i) t += red[i];
        atomicAdd(&g_out_acc, t);
    }
}

// ---------------------------------------------------------------------------
// K3: sa / og full copies with the time-slice replaced (fused, one pass)
// ---------------------------------------------------------------------------
__global__ void k_saog(float* __restrict__ out,
                       const float* __restrict__ sa_in,
                       const float* __restrict__ og_in,
                       const float* __restrict__ ow,
                       const int* __restrict__ time_p) {
    const int time = *time_p;
    const int n = WIDTH * DP1 * TMOD;
    int idx = blockIdx.x * blockDim.x + threadIdx.x;
    if (idx >= n) return;
    int t  = idx % TMOD;
    int wc = idx / TMOD;
    float sav, ogv;
    if (t == time) {
        sav = out[OFF_STATE + wc];
        ogv = ow[wc];
    } else {
        sav = sa_in[idx];
        ogv = og_in[idx];
    }
    out[OFF_SA + idx] = sav;
    out[OFF_OG + idx] = ogv;
}

// ---------------------------------------------------------------------------
// K4: sg + precompute m, act_prev; also publish the output scalar
// ---------------------------------------------------------------------------
__global__ void k_sg(float* __restrict__ out,
                     const float* __restrict__ sa_in,
                     const float* __restrict__ og_in,
                     const float* __restrict__ ow,
                     const int* __restrict__ time_p) {
    int idx = blockIdx.x * blockDim.x + threadIdx.x;   // 0..WD-1
    if (idx >= WIDTH * DEPTH) return;
    if (idx == 0) out[OFF_OUT] = g_out_acc;

    int i = idx >> 3, a = idx & 7;
    const int time = *time_p;
    int tia = posmod(time - 2 * DEPTH + 2 * (a + 1), TMOD);

    float sgv;
    if (a < DEPTH - 1) {
        int t1 = (tia + 1) % TMOD;
        float rm = (sa_eff(sa_in, out, i, a + 2, t1, time) > 0.f) ? 1.f : 0.f;
        // contrib[i,a] lives at slot d = a+1 in the fused layout
        sgv = fmaf(rm, g_contrib[(i << 3) + a + 1], og_eff(og_in, ow, i, a + 1, tia, time));
    } else {
        sgv = ow[(size_t)i * DP1 + DEPTH];
    }
    out[OFF_SG + idx] = sgv;

    float rg = (sa_eff(sa_in, out, i, a + 1, tia, time) > 0.f) ? 1.f : 0.f;
    g_m[idx] = sgv * rg;
    g_aprev[idx] = sa_eff(sa_in, out, i, a, posmod(tia - 1, TMOD), time);
}

// ---------------------------------------------------------------------------
// K5: gradients[i,j,a] = act_prev[i,a] * m[j,a]  (row i flat: ap[k&7]*m[k])
// ---------------------------------------------------------------------------
__global__ void k_grad(float* __restrict__ out) {
    int i = blockIdx.x;
    __shared__ float ap[8];
    if (threadIdx.x < 8) ap[threadIdx.x] = g_aprev[(size_t)i * 8 + threadIdx.x];
    __syncthreads();
    float* dst = out + OFF_GRAD + (size_t)i * WD;
#pragma unroll 4
    for (int k = threadIdx.x; k < WD; k += blockDim.x)
        dst[k] = ap[k & 7] * g_m[k];
}

// ---------------------------------------------------------------------------
extern "C" void kernel_launch(void* const* d_in, const int* in_sizes, int n_in,
                              void* d_out, int out_size) {
    const float* x    = (const float*)d_in[0];
    const float* W    = (const float*)d_in[1];
    const float* ow   = (const float*)d_in[2];
    const float* st   = (const float*)d_in[3];
    const float* sa   = (const float*)d_in[4];
    const float* sgr  = (const float*)d_in[5];
    const float* og   = (const float*)d_in[6];
    const int*   tim  = (const int*)d_in[7];
    float* out = (float*)d_out;

    k_fusedW<<<dim3(KBLK, NSPLIT), 256>>>(W, st, sgr);
    k_finalize<<<WD / 256, 256>>>(out, x, ow);
    k_saog<<<(WIDTH * DP1 * TMOD + 255) / 256, 256>>>(out, sa, og, ow, tim);
    k_sg<<<WD / 256, 256>>>(out, sa, og, ow, tim);
    k_grad<<<WIDTH, 256>>>(out);
}